// round 6
// baseline (speedup 1.0000x reference)
#include <cuda_runtime.h>
#include <cstdint>

#define NB    32
#define NS    1024
#define ROWS  (NB * NS)      // 32768
#define KNN   32
#define NIN   64             // 2*K
#define MID   32

// All weights live in constant memory: warp-uniform accesses compile to
// LDCU (uniform-register path, rt=1) and FFMA takes UR operands directly.
__constant__ __align__(16) float cw1[NIN * MID];  // [64][32] row-major
__constant__ __align__(16) float cb1[MID];
__constant__ __align__(16) float cw2[MID * 2];
__constant__ float cb2[2];
__constant__ float cf1w1[8];
__constant__ float cf1b1[4];
__constant__ float cf1w2[4];
__constant__ float cf1b2[1];

// tanh(x) = 1 - 2/(exp(2x)+1) via ex2.approx + rcp.approx (~1e-6 rel err)
__device__ __forceinline__ float fast_tanh(float x) {
    float e, r;
    asm("ex2.approx.f32 %0, %1;" : "=f"(e) : "f"(x * 2.8853900817779268f));
    asm("rcp.approx.f32 %0, %1;" : "=f"(r) : "f"(e + 1.0f));
    return fmaf(-2.0f, r, 1.0f);
}

__global__ __launch_bounds__(64)
void metak_kernel(const int*   __restrict__ vals,
                  const float* __restrict__ dist,
                  float*       __restrict__ out)
{
    const int row = blockIdx.x * 64 + threadIdx.x;   // grid sized exactly

    // ---- batch ALL global loads up front: 16 x LDG.128, MLP=16 ----
    const float4* dp = reinterpret_cast<const float4*>(dist) + (size_t)row * 8;
    const int4*   vp = reinterpret_cast<const int4*>(vals) + (size_t)row * 8;

    float4 d[8];
    int4   v[8];
#pragma unroll
    for (int i = 0; i < 8; i++) d[i] = dp[i];
#pragma unroll
    for (int i = 0; i < 8; i++) v[i] = vp[i];

    // ---- 32 accumulators, init with bias ----
    float acc[MID];
#pragma unroll
    for (int j = 0; j < MID; j++) acc[j] = cb1[j];

    // ---- Phase A: distances x weight-rows 0..31 ----
#pragma unroll
    for (int i = 0; i < 8; i++) {
#pragma unroll
        for (int e = 0; e < 4; e++) {
            float xv = (e == 0) ? d[i].x : (e == 1) ? d[i].y
                     : (e == 2) ? d[i].z : d[i].w;
            const int k = 4 * i + e;
#pragma unroll
            for (int j = 0; j < MID; j++)
                acc[j] = fmaf(xv, cw1[k * MID + j], acc[j]);
        }
    }

    // ---- Phase B: running distinct-nonzero-label count x weight-rows 32..63 ----
    // labels in [0,100); bit 0 of m0 pre-set so label 0 never counts
    unsigned long long m0 = 1ull, m1 = 0ull;
    int cnt = 0;
#pragma unroll
    for (int i = 0; i < 8; i++) {
#pragma unroll
        for (int e = 0; e < 4; e++) {
            int vv = (e == 0) ? v[i].x : (e == 1) ? v[i].y
                   : (e == 2) ? v[i].z : v[i].w;
            unsigned long long bit = 1ull << (vv & 63);
            bool hi = (vv & 64) != 0;
            unsigned long long cur = hi ? m1 : m0;
            cnt += (int)((cur & bit) == 0ull);
            cur |= bit;
            if (hi) m1 = cur; else m0 = cur;

            float xv = (float)cnt;
            const int k = KNN + 4 * i + e;
#pragma unroll
            for (int j = 0; j < MID; j++)
                acc[j] = fmaf(xv, cw1[k * MID + j], acc[j]);
        }
    }

    // ---- tanh + fc2 layer 2: h[32] @ w2[32,2] + b2 ----
    float o0 = cb2[0], o1 = cb2[1];
#pragma unroll
    for (int j = 0; j < MID; j++) {
        float hj = fast_tanh(acc[j]);
        o0 = fmaf(hj, cw2[2 * j],     o0);
        o1 = fmaf(hj, cw2[2 * j + 1], o1);
    }

    // ---- fc1 head: [o0,o1] -> 4 (tanh) -> 1 ----
    float r = cf1b2[0];
#pragma unroll
    for (int c = 0; c < 4; c++) {
        float t = fast_tanh(fmaf(o1, cf1w1[4 + c], fmaf(o0, cf1w1[c], cf1b1[c])));
        r = fmaf(t, cf1w2[c], r);
    }

    float* op = out + (size_t)row * 3;
    op[0] = o0;
    op[1] = o1;
    op[2] = r;
}

extern "C" void kernel_launch(void* const* d_in, const int* in_sizes, int n_in,
                              void* d_out, int out_size)
{
    const int*   vals = (const int*)  d_in[0];
    const float* dist = (const float*)d_in[1];
    float* out = (float*)d_out;

    // Stage weights into constant memory (D2D async copies: graph-capturable).
    cudaMemcpyToSymbolAsync(cw1,   d_in[2], NIN * MID * sizeof(float), 0, cudaMemcpyDeviceToDevice, 0);
    cudaMemcpyToSymbolAsync(cb1,   d_in[3], MID * sizeof(float),       0, cudaMemcpyDeviceToDevice, 0);
    cudaMemcpyToSymbolAsync(cw2,   d_in[4], MID * 2 * sizeof(float),   0, cudaMemcpyDeviceToDevice, 0);
    cudaMemcpyToSymbolAsync(cb2,   d_in[5], 2 * sizeof(float),         0, cudaMemcpyDeviceToDevice, 0);
    cudaMemcpyToSymbolAsync(cf1w1, d_in[6], 8 * sizeof(float),         0, cudaMemcpyDeviceToDevice, 0);
    cudaMemcpyToSymbolAsync(cf1b1, d_in[7], 4 * sizeof(float),         0, cudaMemcpyDeviceToDevice, 0);
    cudaMemcpyToSymbolAsync(cf1w2, d_in[8], 4 * sizeof(float),         0, cudaMemcpyDeviceToDevice, 0);
    cudaMemcpyToSymbolAsync(cf1b2, d_in[9], 1 * sizeof(float),         0, cudaMemcpyDeviceToDevice, 0);

    const int threads = 64;
    const int blocks  = ROWS / threads;  // 512
    metak_kernel<<<blocks, threads>>>(vals, dist, out);
}